// round 8
// baseline (speedup 1.0000x reference)
#include <cuda_runtime.h>
#include <cstdint>
#include <cstddef>
#include <math.h>

// Problem constants
#define BB 4
#define NN 256
#define FF 1024
#define HH 16
#define KK 128
#define DD 64
#define HID 4096
#define TAB 32

// ---------------- scratch (device globals; no allocation) ----------------
__device__ float g_S[(size_t)BB * HH * NN * NN];
__device__ float g_q[(size_t)BB * HH * NN * DD];
__device__ float g_k[(size_t)BB * HH * NN * DD];
__device__ float g_v[(size_t)BB * HH * NN * DD];
__device__ float g_attn[(size_t)BB * NN * FF];
__device__ float g_x1[(size_t)BB * NN * FF];
__device__ float g_hid[(size_t)BB * NN * HID];
__device__ float g_part[(size_t)4 * BB * NN * FF];   // split-K partials

// ---------------- bias kernel (t1 fused: each CTA recomputes 32x16 table) ----
__global__ void bias_kernel(const int* __restrict__ sp_dist,
                            const float* __restrict__ rd_dist,
                            const float* __restrict__ g_means,
                            const float* __restrict__ g_stds,
                            const float* __restrict__ g_mulp,
                            const float* __restrict__ g_biasp,
                            const float* __restrict__ dist_table,
                            const float* __restrict__ mlp_w1,
                            const float* __restrict__ mlp_b1,
                            const float* __restrict__ mlp_w2,
                            const float* __restrict__ mlp_b2,
                            float* __restrict__ S) {
    __shared__ float w1r[KK][HH];
    __shared__ float t1s[TAB][HH];
    __shared__ float w2s[HH][HH];
    __shared__ float mean_s[KK], istd_s[KK], coef_s[KK];
    __shared__ float b2s[HH];

    int t = threadIdx.x;   // 256
    for (int idx = t; idx < KK * HH; idx += 256)
        w1r[idx >> 4][idx & 15] = mlp_w1[(KK + (idx >> 4)) * HH + (idx & 15)];
    // t1s[sp][h] = sum_k table[sp,k]*w1[k,h] + b1[h]  (2 entries per thread)
    for (int idx = t; idx < TAB * HH; idx += 256) {
        int sp = idx >> 4, h = idx & 15;
        float s = mlp_b1[h];
        for (int k = 0; k < KK; k++)
            s += dist_table[sp * KK + k] * mlp_w1[k * HH + h];
        t1s[sp][h] = s;
    }
    if (t < HH * HH) w2s[t >> 4][t & 15] = mlp_w2[t];
    if (t < KK) {
        float s = fabsf(g_stds[t]) + 0.01f;
        istd_s[t] = 1.0f / s;
        coef_s[t] = 1.0f / (sqrtf(2.0f * 3.14159f) * s);
        mean_s[t] = g_means[t];
    }
    if (t < HH) b2s[t] = mlp_b2[t];
    __syncthreads();

    int bi = blockIdx.x;                    // b*N + i
    int j = t;
    size_t idx = (size_t)bi * NN + j;
    int sp = sp_dist[idx];
    float rd = rd_dist[idx];
    float x = g_mulp[0] * rd + g_biasp[0];

    float acc[HH];
#pragma unroll
    for (int h = 0; h < HH; h++) acc[h] = t1s[sp][h];

    for (int k = 0; k < KK; k++) {
        float dd = (x - mean_s[k]) * istd_s[k];
        float g = expf(-0.5f * dd * dd) * coef_s[k];
#pragma unroll
        for (int h = 0; h < HH; h++) acc[h] += g * w1r[k][h];
    }
#pragma unroll
    for (int h = 0; h < HH; h++) {
        float a = acc[h];
        acc[h] = 0.5f * a * (1.0f + erff(a * 0.70710678118654752f));
    }

    int b = bi >> 8, i = bi & 255;
#pragma unroll
    for (int h2 = 0; h2 < HH; h2++) {
        float o = b2s[h2];
#pragma unroll
        for (int h = 0; h < HH; h++) o += acc[h] * w2s[h][h2];
        S[(((size_t)(b * HH + h2) * NN + i) * NN) + j] = o;
    }
}

// ---------------- TF32 helpers ----------------
__device__ __forceinline__ unsigned f2tf(float f) {
    unsigned u;
    asm("cvt.rna.tf32.f32 %0, %1;" : "=r"(u) : "f"(f));
    return u;
}
__device__ __forceinline__ void split_tf(float f, unsigned& hi, unsigned& lo) {
    hi = f2tf(f);
    lo = f2tf(f - __uint_as_float(hi));
}
__device__ __forceinline__ void mma8(float (&c)[4], const unsigned* a, const unsigned* b) {
    asm volatile(
        "mma.sync.aligned.m16n8k8.row.col.f32.tf32.tf32.f32 "
        "{%0,%1,%2,%3},{%4,%5,%6,%7},{%8,%9},{%0,%1,%2,%3};"
        : "+f"(c[0]), "+f"(c[1]), "+f"(c[2]), "+f"(c[3])
        : "r"(a[0]), "r"(a[1]), "r"(a[2]), "r"(a[3]), "r"(b[0]), "r"(b[1]));
}

// ---------------- TF32 MMA core: 64x64 tile, BK=32, 128 threads ----------------
__device__ __forceinline__ void mma_core(
    const float* __restrict__ Ag, int lda,
    const float* __restrict__ Bg, int ldb, int kLen,
    float (*As)[64][36], float (*Bs)[32][68], float (&c)[2][4][4]) {
    int t = threadIdx.x;
    int warp = t >> 5, lane = t & 31;
    int g = lane >> 2, q = lane & 3;
    int wm = (warp >> 1) * 32, wn = (warp & 1) * 32;

#pragma unroll
    for (int i = 0; i < 2; i++)
#pragma unroll
        for (int j = 0; j < 4; j++)
#pragma unroll
            for (int e = 0; e < 4; e++) c[i][j][e] = 0.f;

    const int KT = kLen / 32;

    auto load_tile = [&](int bufi, int k0) {
#pragma unroll
        for (int i_ = 0; i_ < 4; i_++) {
            int id = t + i_ * 128;
            int row = id >> 3, c4 = id & 7;
            const float* src = Ag + (size_t)row * lda + k0 + c4 * 4;
            unsigned dst = (unsigned)__cvta_generic_to_shared(&As[bufi][row][c4 * 4]);
            asm volatile("cp.async.ca.shared.global [%0], [%1], 16;\n" ::"r"(dst), "l"(src));
        }
#pragma unroll
        for (int i_ = 0; i_ < 4; i_++) {
            int id = t + i_ * 128;
            int row = id >> 4, c4 = id & 15;
            const float* src = Bg + (size_t)(k0 + row) * ldb + c4 * 4;
            unsigned dst = (unsigned)__cvta_generic_to_shared(&Bs[bufi][row][c4 * 4]);
            asm volatile("cp.async.ca.shared.global [%0], [%1], 16;\n" ::"r"(dst), "l"(src));
        }
        asm volatile("cp.async.commit_group;\n" ::);
    };

    load_tile(0, 0);

    for (int kt = 0; kt < KT; kt++) {
        int buf = kt & 1;
        if (kt + 1 < KT) {
            load_tile(buf ^ 1, (kt + 1) * 32);
            asm volatile("cp.async.wait_group 1;\n" ::);
        } else {
            asm volatile("cp.async.wait_group 0;\n" ::);
        }
        __syncthreads();

#pragma unroll
        for (int ks = 0; ks < 4; ks++) {
            unsigned a[2][4], b[4][2];
#pragma unroll
            for (int mt = 0; mt < 2; mt++) {
                int r = wm + mt * 16 + g;
                int k = ks * 8 + q;
                a[mt][0] = f2tf(As[buf][r][k]);
                a[mt][1] = f2tf(As[buf][r + 8][k]);
                a[mt][2] = f2tf(As[buf][r][k + 4]);
                a[mt][3] = f2tf(As[buf][r + 8][k + 4]);
            }
#pragma unroll
            for (int nt = 0; nt < 4; nt++) {
                int n = wn + nt * 8 + g;
                int k = ks * 8 + q;
                b[nt][0] = f2tf(Bs[buf][k][n]);
                b[nt][1] = f2tf(Bs[buf][k + 4][n]);
            }
#pragma unroll
            for (int mt = 0; mt < 2; mt++)
#pragma unroll
                for (int nt = 0; nt < 4; nt++)
                    mma8(c[mt][nt], a[mt], b[nt]);
        }
        __syncthreads();
    }
}

// ---------------- generic GEMM: MODE 0 plain+bias, 1 relu+bias, 3 raw partial ----
template <int MODE>
__global__ void __launch_bounds__(128) mma_gemm(
    const float* __restrict__ A, const float* __restrict__ B,
    const float* __restrict__ bias, float* __restrict__ C,
    int N, int lda, int ldb, int kLen) {
    __shared__ float As[2][64][36];
    __shared__ float Bs[2][32][68];
    int m0 = blockIdx.y * 64, n0 = blockIdx.x * 64;

    int z = blockIdx.z;
    const float* Ag = A + (size_t)m0 * lda + (size_t)z * kLen;
    const float* Bg = B + (size_t)z * kLen * ldb + n0;
    float* Cg = (MODE == 3) ? C + (size_t)z * gridDim.y * 64 * N : C;

    float c[2][4][4];
    mma_core(Ag, lda, Bg, ldb, kLen, As, Bs, c);

    int t = threadIdx.x;
    int warp = t >> 5, lane = t & 31;
    int g = lane >> 2, q = lane & 3;
    int wm = (warp >> 1) * 32, wn = (warp & 1) * 32;

#pragma unroll
    for (int mt = 0; mt < 2; mt++)
#pragma unroll
        for (int nt = 0; nt < 4; nt++)
#pragma unroll
            for (int e = 0; e < 4; e++) {
                int row = m0 + wm + mt * 16 + g + ((e >= 2) ? 8 : 0);
                int col = n0 + wn + nt * 8 + q * 2 + (e & 1);
                float v = c[mt][nt][e];
                if (MODE != 3) v += bias[col];
                if (MODE == 1) v = fmaxf(v, 0.f);
                Cg[(size_t)row * N + col] = v;
            }
}

// ---------------- fused QKV GEMM: grid (48, 16) ----------------
__global__ void __launch_bounds__(128) qkv_gemm(
    const float* __restrict__ A,
    const float* __restrict__ wq, const float* __restrict__ wk, const float* __restrict__ wv,
    const float* __restrict__ bq, const float* __restrict__ bk, const float* __restrict__ bv,
    float* __restrict__ Qo, float* __restrict__ Ko, float* __restrict__ Vo) {
    __shared__ float As[2][64][36];
    __shared__ float Bs[2][32][68];
    int mat = blockIdx.x >> 4;
    int n0 = (blockIdx.x & 15) * 64, m0 = blockIdx.y * 64;
    const float* B = (mat == 0) ? wq : (mat == 1) ? wk : wv;
    const float* bias = (mat == 0) ? bq : (mat == 1) ? bk : bv;
    float* C = (mat == 0) ? Qo : (mat == 1) ? Ko : Vo;
    float scale = (mat == 0) ? 8.0f : 1.0f;

    const float* Ag = A + (size_t)m0 * FF;
    const float* Bg = B + n0;

    float c[2][4][4];
    mma_core(Ag, FF, Bg, FF, FF, As, Bs, c);

    int t = threadIdx.x;
    int warp = t >> 5, lane = t & 31;
    int g = lane >> 2, q = lane & 3;
    int wm = (warp >> 1) * 32, wn = (warp & 1) * 32;

#pragma unroll
    for (int mt = 0; mt < 2; mt++)
#pragma unroll
        for (int nt = 0; nt < 4; nt++)
#pragma unroll
            for (int e = 0; e < 4; e++) {
                int row = m0 + wm + mt * 16 + g + ((e >= 2) ? 8 : 0);
                int col = n0 + wn + nt * 8 + q * 2 + (e & 1);
                float v = (c[mt][nt][e] + bias[col]) * scale;
                int b_ = row >> 8, ii = row & 255, h = col >> 6, d = col & 63;
                C[(((size_t)(b_ * HH + h) * NN + ii) * DD) + d] = v;
            }
}

// ---------------- fused flash attention, pre-split tf32 smem planes ----------
// grid (8, 64): blockIdx.x = i-tile (32 rows), blockIdx.y = b*H+h. 128 threads.
// Warps 2x2 over the 32x64 S tile: warp tile 16x32.
// smem planes (all stride 68): Qhi/Qlo [32], Khi/Klo [64] (transposed [d][j]),
// Vs [64] (tf32 bits). P (tf32 bits) reuses Khi rows 0..31.
#define SM_QHI 0
#define SM_QLO (32 * 68)
#define SM_KHI (2 * 32 * 68)
#define SM_KLO (2 * 32 * 68 + 64 * 68)
#define SM_VS  (2 * 32 * 68 + 2 * 64 * 68)
#define SM_RED (2 * 32 * 68 + 3 * 64 * 68)
#define ATTN_SMEM ((2 * 32 * 68 + 3 * 64 * 68 + 64) * 4)
__global__ void __launch_bounds__(128) attn_kernel(
    const float* __restrict__ Q, const float* __restrict__ K,
    const float* __restrict__ V, const float* __restrict__ Sb,
    float* __restrict__ O) {
    extern __shared__ float sm[];
    unsigned* Qhi = (unsigned*)sm + SM_QHI;
    unsigned* Qlo = (unsigned*)sm + SM_QLO;
    unsigned* Khi = (unsigned*)sm + SM_KHI;   // also P after S-MMA
    unsigned* Klo = (unsigned*)sm + SM_KLO;
    unsigned* Vs  = (unsigned*)sm + SM_VS;
    float*    red = sm + SM_RED;

    int bh = blockIdx.y;
    int b = bh >> 4, h = bh & 15;
    int i0 = blockIdx.x * 32;
    const float* Qg = Q + (size_t)bh * NN * DD + (size_t)i0 * DD;
    const float* Kg = K + (size_t)bh * NN * DD;
    const float* Vg = V + (size_t)bh * NN * DD;
    const float* Bg = Sb + (size_t)bh * NN * NN + (size_t)i0 * NN;

    int t = threadIdx.x;
    int warp = t >> 5, lane = t & 31;
    int g = lane >> 2, q = lane & 3;
    int wm = (warp >> 1) * 16, wn = (warp & 1) * 32;
    int r0 = wm + g, r1 = wm + g + 8;

    // load + split Q tile [32][64] once
#pragma unroll
    for (int r = 0; r < 4; r++) {
        int id = t + r * 128;
        int row = id >> 4, c4 = (id & 15) * 4;
        float4 qv = *(const float4*)(Qg + (size_t)row * DD + c4);
        unsigned hi, lo;
        split_tf(qv.x, hi, lo); Qhi[row * 68 + c4 + 0] = hi; Qlo[row * 68 + c4 + 0] = lo;
        split_tf(qv.y, hi, lo); Qhi[row * 68 + c4 + 1] = hi; Qlo[row * 68 + c4 + 1] = lo;
        split_tf(qv.z, hi, lo); Qhi[row * 68 + c4 + 2] = hi; Qlo[row * 68 + c4 + 2] = lo;
        split_tf(qv.w, hi, lo); Qhi[row * 68 + c4 + 3] = hi; Qlo[row * 68 + c4 + 3] = lo;
    }

    float o[4][4];
#pragma unroll
    for (int nt = 0; nt < 4; nt++)
#pragma unroll
        for (int e = 0; e < 4; e++) o[nt][e] = 0.f;
    float mrun[2] = {-1e30f, -1e30f};
    float lrun[2] = {0.f, 0.f};

    for (int jt = 0; jt < 4; jt++) {
        int j0 = jt * 64;
        __syncthreads();    // prior PV reads of Khi(P)/Vs done; Qhi/Qlo ready
        // K^T tile split: Khi/Klo[d][j] = split(K[j0+j][d])
#pragma unroll
        for (int r = 0; r < 8; r++) {
            int id = t + r * 128;
            int row = id >> 4, c4 = (id & 15) * 4;
            float4 kv = *(const float4*)(Kg + (size_t)(j0 + row) * DD + c4);
            unsigned hi, lo;
            split_tf(kv.x, hi, lo); Khi[(c4 + 0) * 68 + row] = hi; Klo[(c4 + 0) * 68 + row] = lo;
            split_tf(kv.y, hi, lo); Khi[(c4 + 1) * 68 + row] = hi; Klo[(c4 + 1) * 68 + row] = lo;
            split_tf(kv.z, hi, lo); Khi[(c4 + 2) * 68 + row] = hi; Klo[(c4 + 2) * 68 + row] = lo;
            split_tf(kv.w, hi, lo); Khi[(c4 + 3) * 68 + row] = hi; Klo[(c4 + 3) * 68 + row] = lo;
        }
        // V tile as tf32 bits: Vs[j][d]
#pragma unroll
        for (int r = 0; r < 8; r++) {
            int id = t + r * 128;
            int row = id >> 4, c4 = (id & 15) * 4;
            float4 vv = *(const float4*)(Vg + (size_t)(j0 + row) * DD + c4);
            uint4 u = {f2tf(vv.x), f2tf(vv.y), f2tf(vv.z), f2tf(vv.w)};
            *(uint4*)&Vs[row * 68 + c4] = u;
        }
        __syncthreads();

        // init c with bias fragment
        float c[4][4];
#pragma unroll
        for (int nt = 0; nt < 4; nt++) {
            int col = j0 + wn + nt * 8 + q * 2;
            float2 b0 = *(const float2*)(Bg + (size_t)r0 * NN + col);
            float2 b1 = *(const float2*)(Bg + (size_t)r1 * NN + col);
            c[nt][0] = b0.x; c[nt][1] = b0.y;
            c[nt][2] = b1.x; c[nt][3] = b1.y;
        }

        // S += Q @ K^T via 3xTF32 — pure LDS + MMA
#pragma unroll
        for (int ks = 0; ks < 8; ks++) {
            int k = ks * 8 + q;
            unsigned ah[4], al[4], bh_[4][2], bl[4][2];
            ah[0] = Qhi[r0 * 68 + k];     al[0] = Qlo[r0 * 68 + k];
            ah[1] = Qhi[r1 * 68 + k];     al[1] = Qlo[r1 * 68 + k];
            ah[2] = Qhi[r0 * 68 + k + 4]; al[2] = Qlo[r0 * 68 + k + 4];
            ah[3] = Qhi[r1 * 68 + k + 4]; al[3] = Qlo[r1 * 68 + k + 4];
#pragma unroll
            for (int nt = 0; nt < 4; nt++) {
                int n = wn + nt * 8 + g;
                bh_[nt][0] = Khi[k * 68 + n];       bl[nt][0] = Klo[k * 68 + n];
                bh_[nt][1] = Khi[(k + 4) * 68 + n]; bl[nt][1] = Klo[(k + 4) * 68 + n];
            }
#pragma unroll
            for (int nt = 0; nt < 4; nt++) {
                mma8(c[nt], ah, bh_[nt]);
                mma8(c[nt], ah, bl[nt]);
                mma8(c[nt], al, bh_[nt]);
            }
        }

        // ---- online softmax ----
        float tmax[2] = {-1e30f, -1e30f};
#pragma unroll
        for (int nt = 0; nt < 4; nt++)
#pragma unroll
            for (int e = 0; e < 4; e++)
                tmax[e >> 1] = fmaxf(tmax[e >> 1], c[nt][e]);
#pragma unroll
        for (int s = 1; s < 4; s <<= 1)
#pragma unroll
            for (int i = 0; i < 2; i++)
                tmax[i] = fmaxf(tmax[i], __shfl_xor_sync(0xffffffffu, tmax[i], s));
        if (q == 0) {
            red[(warp & 1) * 32 + r0] = tmax[0];
            red[(warp & 1) * 32 + r1] = tmax[1];
        }
        __syncthreads();   // also: all warps past S-MMA (Khi reads done)
        float scale[2];
#pragma unroll
        for (int i = 0; i < 2; i++) {
            int rr = wm + i * 8 + g;
            float tm = fmaxf(red[rr], red[32 + rr]);
            float mnew = fmaxf(mrun[i], tm);
            scale[i] = expf(mrun[i] - mnew);
            mrun[i] = mnew;
        }
        __syncthreads();   // red reads done before sum-phase writes

        float tsum[2] = {0.f, 0.f};
#pragma unroll
        for (int nt = 0; nt < 4; nt++)
#pragma unroll
            for (int e = 0; e < 4; e++) {
                float p = expf(c[nt][e] - mrun[e >> 1]);
                c[nt][e] = p;
                tsum[e >> 1] += p;
            }
#pragma unroll
        for (int s = 1; s < 4; s <<= 1)
#pragma unroll
            for (int i = 0; i < 2; i++)
                tsum[i] += __shfl_xor_sync(0xffffffffu, tsum[i], s);
        if (q == 0) {
            red[(warp & 1) * 32 + r0] = tsum[0];
            red[(warp & 1) * 32 + r1] = tsum[1];
        }
        // write P (tf32 bits) into Khi rows 0..31 (K dead after S-MMA)
#pragma unroll
        for (int nt = 0; nt < 4; nt++) {
            int col = wn + nt * 8 + q * 2;
            Khi[r0 * 68 + col]     = f2tf(c[nt][0]);
            Khi[r0 * 68 + col + 1] = f2tf(c[nt][1]);
            Khi[r1 * 68 + col]     = f2tf(c[nt][2]);
            Khi[r1 * 68 + col + 1] = f2tf(c[nt][3]);
        }
        __syncthreads();

#pragma unroll
        for (int i = 0; i < 2; i++) {
            int rr = wm + i * 8 + g;
            lrun[i] = lrun[i] * scale[i] + red[rr] + red[32 + rr];
        }
        // rescale O, then O += P @ V — pure LDS + MMA
#pragma unroll
        for (int nt = 0; nt < 4; nt++)
#pragma unroll
            for (int e = 0; e < 4; e++)
                o[nt][e] *= scale[e >> 1];
#pragma unroll
        for (int ks = 0; ks < 8; ks++) {
            int k = ks * 8 + q;
            unsigned a[4], bb[4][2];
            a[0] = Khi[r0 * 68 + k];
            a[1] = Khi[r1 * 68 + k];
            a[2] = Khi[r0 * 68 + k + 4];
            a[3] = Khi[r1 * 68 + k + 4];
#pragma unroll
            for (int nt = 0; nt < 4; nt++) {
                int n = wn + nt * 8 + g;
                bb[nt][0] = Vs[k * 68 + n];
                bb[nt][1] = Vs[(k + 4) * 68 + n];
            }
#pragma unroll
            for (int nt = 0; nt < 4; nt++)
                mma8(o[nt], a, bb[nt]);
        }
    }

    // epilogue: O /= l, write to attn concat [b][i][h*64+d]
    float* Og = O + ((size_t)(b * NN + i0)) * FF + h * DD;
    float il0 = 1.0f / lrun[0];
    float il1 = 1.0f / lrun[1];
#pragma unroll
    for (int nt = 0; nt < 4; nt++) {
        int col = wn + nt * 8 + q * 2;
        float2 v0 = {o[nt][0] * il0, o[nt][1] * il0};
        *(float2*)(Og + (size_t)r0 * FF + col) = v0;
        float2 v1 = {o[nt][2] * il1, o[nt][3] * il1};
        *(float2*)(Og + (size_t)r1 * FF + col) = v1;
    }
}

// ---------------- out = LayerNorm(A + bias + sum_p part[p]) ----------------
template <int P>
__global__ void add_lnp_kernel(const float* __restrict__ A, const float* __restrict__ part,
                               const float* __restrict__ bias,
                               const float* __restrict__ g, const float* __restrict__ be,
                               float* __restrict__ out) {
    int row = blockIdx.x, t = threadIdx.x;
    const float* a = A + (size_t)row * FF;
    __shared__ float red[256];
    float v[4];
    float s = 0.f;
#pragma unroll
    for (int k = 0; k < 4; k++) {
        int c = t + k * 256;
        float acc = a[c] + bias[c];
#pragma unroll
        for (int p = 0; p < P; p++)
            acc += part[(size_t)p * BB * NN * FF + (size_t)row * FF + c];
        v[k] = acc;
        s += acc;
    }
    red[t] = s;
    __syncthreads();
#pragma unroll
    for (int st = 128; st > 0; st >>= 1) {
        if (t < st) red[t] += red[t + st];
        __syncthreads();
    }
    float mean = red[0] * (1.0f / FF);
    __syncthreads();
    float sq = 0.f;
#pragma unroll
    for (int k = 0; k < 4; k++) {
        float d = v[k] - mean;
        sq += d * d;
    }
    red[t] = sq;
    __syncthreads();
#pragma unroll
    for (int st = 128; st > 0; st >>= 1) {
        if (t < st) red[t] += red[t + st];
        __syncthreads();
    }
    float inv = rsqrtf(red[0] * (1.0f / FF) + 1e-5f);
#pragma unroll
    for (int k = 0; k < 4; k++) {
        int c = t + k * 256;
        out[(size_t)row * FF + c] = (v[k] - mean) * inv * g[c] + be[c];
    }
}

// ---------------- launch ----------------
extern "C" void kernel_launch(void* const* d_in, const int* in_sizes, int n_in,
                              void* d_out, int out_size) {
    const float* nfeat      = (const float*)d_in[0];
    const int*   sp_dist    = (const int*)d_in[1];
    const float* rd_dist    = (const float*)d_in[2];
    const float* dist_table = (const float*)d_in[3];
    const float* g_means    = (const float*)d_in[4];
    const float* g_stds     = (const float*)d_in[5];
    const float* g_mul      = (const float*)d_in[6];
    const float* g_biasv    = (const float*)d_in[7];
    const float* mlp_w1     = (const float*)d_in[8];
    const float* mlp_b1     = (const float*)d_in[9];
    const float* mlp_w2     = (const float*)d_in[10];
    const float* mlp_b2     = (const float*)d_in[11];
    const float* wq = (const float*)d_in[12];  const float* bq = (const float*)d_in[13];
    const float* wk = (const float*)d_in[14];  const float* bk = (const float*)d_in[15];
    const float* wv = (const float*)d_in[16];  const float* bv = (const float*)d_in[17];
    const float* wo = (const float*)d_in[18];  const float* bo = (const float*)d_in[19];
    const float* ffn_w1 = (const float*)d_in[20]; const float* ffn_b1 = (const float*)d_in[21];
    const float* ffn_w2 = (const float*)d_in[22]; const float* ffn_b2 = (const float*)d_in[23];
    const float* ln1_g = (const float*)d_in[24]; const float* ln1_b = (const float*)d_in[25];
    const float* ln2_g = (const float*)d_in[26]; const float* ln2_b = (const float*)d_in[27];

    void *pS, *pQ, *pK, *pV, *pAttn, *pX1, *pHid, *pPart;
    cudaGetSymbolAddress(&pS, g_S);
    cudaGetSymbolAddress(&pQ, g_q);
    cudaGetSymbolAddress(&pK, g_k);
    cudaGetSymbolAddress(&pV, g_v);
    cudaGetSymbolAddress(&pAttn, g_attn);
    cudaGetSymbolAddress(&pX1, g_x1);
    cudaGetSymbolAddress(&pHid, g_hid);
    cudaGetSymbolAddress(&pPart, g_part);

    float* S = (float*)pS; float* Q = (float*)pQ; float* Kb = (float*)pK;
    float* V = (float*)pV; float* At = (float*)pAttn;
    float* X1 = (float*)pX1; float* Hd = (float*)pHid;
    float* Pt = (float*)pPart;

    static cudaStream_t s1;
    static cudaEvent_t evFork, evJoin;
    static bool init_done = false;
    if (!init_done) {
        cudaFuncSetAttribute(attn_kernel, cudaFuncAttributeMaxDynamicSharedMemorySize,
                             ATTN_SMEM);
        cudaStreamCreateWithFlags(&s1, cudaStreamNonBlocking);
        cudaEventCreateWithFlags(&evFork, cudaEventDisableTiming);
        cudaEventCreateWithFlags(&evJoin, cudaEventDisableTiming);
        init_done = true;
    }

    // fork: dist-encoder bias on s1, QKV on main stream (independent)
    cudaEventRecord(evFork, 0);
    cudaStreamWaitEvent(s1, evFork, 0);
    bias_kernel<<<BB * NN, 256, 0, s1>>>(sp_dist, rd_dist, g_means, g_stds, g_mul,
                                         g_biasv, dist_table, mlp_w1, mlp_b1,
                                         mlp_w2, mlp_b2, S);
    cudaEventRecord(evJoin, s1);

    // QKV projections on main stream (q scaled by sqrt(D)=8 per reference)
    qkv_gemm<<<dim3(48, 16), 128>>>(nfeat, wq, wk, wv, bq, bk, bv, Q, Kb, V);

    // join: attention needs both bias (s1) and QKV (main)
    cudaStreamWaitEvent(0, evJoin, 0);
    attn_kernel<<<dim3(8, BB * HH), 128, ATTN_SMEM>>>(Q, Kb, V, S, At);

    // output projection (split-K=4 partials) + LN1
    mma_gemm<3><<<dim3(16, 16, 4), 128>>>(At, wo, nullptr, Pt, FF, FF, FF, FF / 4);
    add_lnp_kernel<4><<<BB * NN, 256>>>(nfeat, Pt, bo, ln1_g, ln1_b, X1);

    // FFN: w1+relu direct, w2 split-K=4 partials + LN2
    mma_gemm<1><<<dim3(64, 16, 1), 128>>>(X1, ffn_w1, ffn_b1, Hd, HID, FF, HID, FF);
    mma_gemm<3><<<dim3(16, 16, 4), 128>>>(Hd, ffn_w2, nullptr, Pt, FF, HID, FF, HID / 4);
    add_lnp_kernel<4><<<BB * NN, 256>>>(X1, Pt, ffn_b2, ln2_g, ln2_b, (float*)d_out);
}

// round 9
// speedup vs baseline: 1.0566x; 1.0566x over previous
#include <cuda_runtime.h>
#include <cstdint>
#include <cstddef>
#include <math.h>

// Problem constants
#define BB 4
#define NN 256
#define FF 1024
#define HH 16
#define KK 128
#define DD 64
#define HID 4096
#define TAB 32

// ---------------- scratch (device globals; no allocation) ----------------
__device__ float g_S[(size_t)BB * HH * NN * NN];
__device__ float g_q[(size_t)BB * HH * NN * DD];
__device__ float g_k[(size_t)BB * HH * NN * DD];
__device__ float g_v[(size_t)BB * HH * NN * DD];
__device__ float g_attn[(size_t)BB * NN * FF];
__device__ float g_x1[(size_t)BB * NN * FF];
__device__ float g_hid[(size_t)BB * NN * HID];
__device__ float g_part[(size_t)4 * BB * NN * FF];   // split-K partials

// ---------------- bias kernel (t1 fused: each CTA recomputes 32x16 table) ----
__global__ void bias_kernel(const int* __restrict__ sp_dist,
                            const float* __restrict__ rd_dist,
                            const float* __restrict__ g_means,
                            const float* __restrict__ g_stds,
                            const float* __restrict__ g_mulp,
                            const float* __restrict__ g_biasp,
                            const float* __restrict__ dist_table,
                            const float* __restrict__ mlp_w1,
                            const float* __restrict__ mlp_b1,
                            const float* __restrict__ mlp_w2,
                            const float* __restrict__ mlp_b2,
                            float* __restrict__ S) {
    __shared__ float w1r[KK][HH];
    __shared__ float t1s[TAB][HH];
    __shared__ float w2s[HH][HH];
    __shared__ float mean_s[KK], istd_s[KK], coef_s[KK];
    __shared__ float b2s[HH];

    int t = threadIdx.x;   // 256
    for (int idx = t; idx < KK * HH; idx += 256)
        w1r[idx >> 4][idx & 15] = mlp_w1[(KK + (idx >> 4)) * HH + (idx & 15)];
    // t1s[sp][h] = sum_k table[sp,k]*w1[k,h] + b1[h]  (2 entries per thread)
    for (int idx = t; idx < TAB * HH; idx += 256) {
        int sp = idx >> 4, h = idx & 15;
        float s = mlp_b1[h];
        for (int k = 0; k < KK; k++)
            s += dist_table[sp * KK + k] * mlp_w1[k * HH + h];
        t1s[sp][h] = s;
    }
    if (t < HH * HH) w2s[t >> 4][t & 15] = mlp_w2[t];
    if (t < KK) {
        float s = fabsf(g_stds[t]) + 0.01f;
        istd_s[t] = 1.0f / s;
        coef_s[t] = 1.0f / (sqrtf(2.0f * 3.14159f) * s);
        mean_s[t] = g_means[t];
    }
    if (t < HH) b2s[t] = mlp_b2[t];
    __syncthreads();

    int bi = blockIdx.x;                    // b*N + i
    int j = t;
    size_t idx = (size_t)bi * NN + j;
    int sp = sp_dist[idx];
    float rd = rd_dist[idx];
    float x = g_mulp[0] * rd + g_biasp[0];

    float acc[HH];
#pragma unroll
    for (int h = 0; h < HH; h++) acc[h] = t1s[sp][h];

    for (int k = 0; k < KK; k++) {
        float dd = (x - mean_s[k]) * istd_s[k];
        float g = expf(-0.5f * dd * dd) * coef_s[k];
#pragma unroll
        for (int h = 0; h < HH; h++) acc[h] += g * w1r[k][h];
    }
#pragma unroll
    for (int h = 0; h < HH; h++) {
        float a = acc[h];
        acc[h] = 0.5f * a * (1.0f + erff(a * 0.70710678118654752f));
    }

    int b = bi >> 8, i = bi & 255;
#pragma unroll
    for (int h2 = 0; h2 < HH; h2++) {
        float o = b2s[h2];
#pragma unroll
        for (int h = 0; h < HH; h++) o += acc[h] * w2s[h][h2];
        S[(((size_t)(b * HH + h2) * NN + i) * NN) + j] = o;
    }
}

// ---------------- TF32 helpers ----------------
__device__ __forceinline__ unsigned f2tf(float f) {
    unsigned u;
    asm("cvt.rna.tf32.f32 %0, %1;" : "=r"(u) : "f"(f));
    return u;
}
__device__ __forceinline__ void split_tf(float f, unsigned& hi, unsigned& lo) {
    hi = f2tf(f);
    lo = f2tf(f - __uint_as_float(hi));
}
__device__ __forceinline__ void mma8(float (&c)[4], const unsigned* a, const unsigned* b) {
    asm volatile(
        "mma.sync.aligned.m16n8k8.row.col.f32.tf32.tf32.f32 "
        "{%0,%1,%2,%3},{%4,%5,%6,%7},{%8,%9},{%0,%1,%2,%3};"
        : "+f"(c[0]), "+f"(c[1]), "+f"(c[2]), "+f"(c[3])
        : "r"(a[0]), "r"(a[1]), "r"(a[2]), "r"(a[3]), "r"(b[0]), "r"(b[1]));
}

// ---------------- TF32 MMA core: 64x64 tile, BK=32, 128 threads ----------------
__device__ __forceinline__ void mma_core(
    const float* __restrict__ Ag, int lda,
    const float* __restrict__ Bg, int ldb, int kLen,
    float (*As)[64][36], float (*Bs)[32][68], float (&c)[2][4][4]) {
    int t = threadIdx.x;
    int warp = t >> 5, lane = t & 31;
    int g = lane >> 2, q = lane & 3;
    int wm = (warp >> 1) * 32, wn = (warp & 1) * 32;

#pragma unroll
    for (int i = 0; i < 2; i++)
#pragma unroll
        for (int j = 0; j < 4; j++)
#pragma unroll
            for (int e = 0; e < 4; e++) c[i][j][e] = 0.f;

    const int KT = kLen / 32;

    auto load_tile = [&](int bufi, int k0) {
#pragma unroll
        for (int i_ = 0; i_ < 4; i_++) {
            int id = t + i_ * 128;
            int row = id >> 3, c4 = id & 7;
            const float* src = Ag + (size_t)row * lda + k0 + c4 * 4;
            unsigned dst = (unsigned)__cvta_generic_to_shared(&As[bufi][row][c4 * 4]);
            asm volatile("cp.async.ca.shared.global [%0], [%1], 16;\n" ::"r"(dst), "l"(src));
        }
#pragma unroll
        for (int i_ = 0; i_ < 4; i_++) {
            int id = t + i_ * 128;
            int row = id >> 4, c4 = id & 15;
            const float* src = Bg + (size_t)(k0 + row) * ldb + c4 * 4;
            unsigned dst = (unsigned)__cvta_generic_to_shared(&Bs[bufi][row][c4 * 4]);
            asm volatile("cp.async.ca.shared.global [%0], [%1], 16;\n" ::"r"(dst), "l"(src));
        }
        asm volatile("cp.async.commit_group;\n" ::);
    };

    load_tile(0, 0);

    for (int kt = 0; kt < KT; kt++) {
        int buf = kt & 1;
        if (kt + 1 < KT) {
            load_tile(buf ^ 1, (kt + 1) * 32);
            asm volatile("cp.async.wait_group 1;\n" ::);
        } else {
            asm volatile("cp.async.wait_group 0;\n" ::);
        }
        __syncthreads();

#pragma unroll
        for (int ks = 0; ks < 4; ks++) {
            unsigned a[2][4], b[4][2];
#pragma unroll
            for (int mt = 0; mt < 2; mt++) {
                int r = wm + mt * 16 + g;
                int k = ks * 8 + q;
                a[mt][0] = f2tf(As[buf][r][k]);
                a[mt][1] = f2tf(As[buf][r + 8][k]);
                a[mt][2] = f2tf(As[buf][r][k + 4]);
                a[mt][3] = f2tf(As[buf][r + 8][k + 4]);
            }
#pragma unroll
            for (int nt = 0; nt < 4; nt++) {
                int n = wn + nt * 8 + g;
                int k = ks * 8 + q;
                b[nt][0] = f2tf(Bs[buf][k][n]);
                b[nt][1] = f2tf(Bs[buf][k + 4][n]);
            }
#pragma unroll
            for (int mt = 0; mt < 2; mt++)
#pragma unroll
                for (int nt = 0; nt < 4; nt++)
                    mma8(c[mt][nt], a[mt], b[nt]);
        }
        __syncthreads();
    }
}

// ---------------- generic GEMM: MODE 0 plain+bias, 1 relu+bias, 3 raw partial ----
template <int MODE>
__global__ void __launch_bounds__(128) mma_gemm(
    const float* __restrict__ A, const float* __restrict__ B,
    const float* __restrict__ bias, float* __restrict__ C,
    int N, int lda, int ldb, int kLen) {
    __shared__ float As[2][64][36];
    __shared__ float Bs[2][32][68];
    int m0 = blockIdx.y * 64, n0 = blockIdx.x * 64;

    int z = blockIdx.z;
    const float* Ag = A + (size_t)m0 * lda + (size_t)z * kLen;
    const float* Bg = B + (size_t)z * kLen * ldb + n0;
    float* Cg = (MODE == 3) ? C + (size_t)z * gridDim.y * 64 * N : C;

    float c[2][4][4];
    mma_core(Ag, lda, Bg, ldb, kLen, As, Bs, c);

    int t = threadIdx.x;
    int warp = t >> 5, lane = t & 31;
    int g = lane >> 2, q = lane & 3;
    int wm = (warp >> 1) * 32, wn = (warp & 1) * 32;

#pragma unroll
    for (int mt = 0; mt < 2; mt++)
#pragma unroll
        for (int nt = 0; nt < 4; nt++)
#pragma unroll
            for (int e = 0; e < 4; e++) {
                int row = m0 + wm + mt * 16 + g + ((e >= 2) ? 8 : 0);
                int col = n0 + wn + nt * 8 + q * 2 + (e & 1);
                float v = c[mt][nt][e];
                if (MODE != 3) v += bias[col];
                if (MODE == 1) v = fmaxf(v, 0.f);
                Cg[(size_t)row * N + col] = v;
            }
}

// ---------------- fused QKV GEMM: grid (48, 16) ----------------
__global__ void __launch_bounds__(128) qkv_gemm(
    const float* __restrict__ A,
    const float* __restrict__ wq, const float* __restrict__ wk, const float* __restrict__ wv,
    const float* __restrict__ bq, const float* __restrict__ bk, const float* __restrict__ bv,
    float* __restrict__ Qo, float* __restrict__ Ko, float* __restrict__ Vo) {
    __shared__ float As[2][64][36];
    __shared__ float Bs[2][32][68];
    int mat = blockIdx.x >> 4;
    int n0 = (blockIdx.x & 15) * 64, m0 = blockIdx.y * 64;
    const float* B = (mat == 0) ? wq : (mat == 1) ? wk : wv;
    const float* bias = (mat == 0) ? bq : (mat == 1) ? bk : bv;
    float* C = (mat == 0) ? Qo : (mat == 1) ? Ko : Vo;
    float scale = (mat == 0) ? 8.0f : 1.0f;

    const float* Ag = A + (size_t)m0 * FF;
    const float* Bg = B + n0;

    float c[2][4][4];
    mma_core(Ag, FF, Bg, FF, FF, As, Bs, c);

    int t = threadIdx.x;
    int warp = t >> 5, lane = t & 31;
    int g = lane >> 2, q = lane & 3;
    int wm = (warp >> 1) * 32, wn = (warp & 1) * 32;

#pragma unroll
    for (int mt = 0; mt < 2; mt++)
#pragma unroll
        for (int nt = 0; nt < 4; nt++)
#pragma unroll
            for (int e = 0; e < 4; e++) {
                int row = m0 + wm + mt * 16 + g + ((e >= 2) ? 8 : 0);
                int col = n0 + wn + nt * 8 + q * 2 + (e & 1);
                float v = (c[mt][nt][e] + bias[col]) * scale;
                int b_ = row >> 8, ii = row & 255, h = col >> 6, d = col & 63;
                C[(((size_t)(b_ * HH + h) * NN + ii) * DD) + d] = v;
            }
}

// ---------------- fused flash attention (64-row i-tiles, split-in-register) ----
// grid (4, 64): blockIdx.x = i-tile (64 rows), blockIdx.y = b*H+h. 128 threads.
// S = Q@K^T (3xTF32) + bias; online softmax; O = P@V (tf32).
#define ATTN_SMEM (3 * 64 * 68 * 4 + 2 * 64 * 4)
__global__ void __launch_bounds__(128) attn_kernel(
    const float* __restrict__ Q, const float* __restrict__ K,
    const float* __restrict__ V, const float* __restrict__ Sb,
    float* __restrict__ O) {
    extern __shared__ float sm[];
    float* Qs  = sm;                 // [64][68]  Q tile  [i][d]
    float* KPs = sm + 64 * 68;       // [64][68]  K^T [d][j], then P [i][j]
    float* Vs  = sm + 2 * 64 * 68;   // [64][68]  V tile [j][d]
    float* red = sm + 3 * 64 * 68;   // [2][64]   cross-warp row reduction

    int bh = blockIdx.y;
    int b = bh >> 4, h = bh & 15;
    int i0 = blockIdx.x * 64;
    const float* Qg = Q + (size_t)bh * NN * DD + (size_t)i0 * DD;
    const float* Kg = K + (size_t)bh * NN * DD;
    const float* Vg = V + (size_t)bh * NN * DD;
    const float* Bg = Sb + (size_t)bh * NN * NN + (size_t)i0 * NN;

    int t = threadIdx.x;
    int warp = t >> 5, lane = t & 31;
    int g = lane >> 2, q = lane & 3;
    int wm = (warp >> 1) * 32, wn = (warp & 1) * 32;

    // load Q tile [64][64]
#pragma unroll
    for (int r = 0; r < 8; r++) {
        int id = t + r * 128;
        int row = id >> 4, c4 = (id & 15) * 4;
        *(float4*)&Qs[row * 68 + c4] = *(const float4*)(Qg + (size_t)row * DD + c4);
    }

    float o[2][4][4];
#pragma unroll
    for (int mt = 0; mt < 2; mt++)
#pragma unroll
        for (int nt = 0; nt < 4; nt++)
#pragma unroll
            for (int e = 0; e < 4; e++) o[mt][nt][e] = 0.f;
    float mrun[4] = {-1e30f, -1e30f, -1e30f, -1e30f};
    float lrun[4] = {0.f, 0.f, 0.f, 0.f};

    for (int jt = 0; jt < 4; jt++) {
        int j0 = jt * 64;
        __syncthreads();    // prior PV reads of KPs/Vs done; Qs ready
        // K^T tile: KPs[d][j] = K[j0+j][d]
#pragma unroll
        for (int r = 0; r < 8; r++) {
            int id = t + r * 128;
            int row = id >> 4, c4 = (id & 15) * 4;
            float4 kv = *(const float4*)(Kg + (size_t)(j0 + row) * DD + c4);
            KPs[(c4 + 0) * 68 + row] = kv.x;
            KPs[(c4 + 1) * 68 + row] = kv.y;
            KPs[(c4 + 2) * 68 + row] = kv.z;
            KPs[(c4 + 3) * 68 + row] = kv.w;
        }
        // V tile: Vs[j][d]
#pragma unroll
        for (int r = 0; r < 8; r++) {
            int id = t + r * 128;
            int row = id >> 4, c4 = (id & 15) * 4;
            *(float4*)&Vs[row * 68 + c4] = *(const float4*)(Vg + (size_t)(j0 + row) * DD + c4);
        }
        __syncthreads();

        // init c with bias fragment
        float c[2][4][4];
#pragma unroll
        for (int mt = 0; mt < 2; mt++)
#pragma unroll
            for (int nt = 0; nt < 4; nt++) {
                int row0 = wm + mt * 16 + g;
                int col = j0 + wn + nt * 8 + q * 2;
                float2 b0 = *(const float2*)(Bg + (size_t)row0 * NN + col);
                float2 b1 = *(const float2*)(Bg + (size_t)(row0 + 8) * NN + col);
                c[mt][nt][0] = b0.x; c[mt][nt][1] = b0.y;
                c[mt][nt][2] = b1.x; c[mt][nt][3] = b1.y;
            }

        // S += Q @ K^T via 3xTF32 (hi*hi + hi*lo + lo*hi)
#pragma unroll
        for (int ks = 0; ks < 8; ks++) {
            unsigned ah[2][4], al[2][4], bh_[4][2], bl[4][2];
#pragma unroll
            for (int mt = 0; mt < 2; mt++) {
                int r = wm + mt * 16 + g;
                int k = ks * 8 + q;
                split_tf(Qs[r * 68 + k],        ah[mt][0], al[mt][0]);
                split_tf(Qs[(r + 8) * 68 + k],  ah[mt][1], al[mt][1]);
                split_tf(Qs[r * 68 + k + 4],    ah[mt][2], al[mt][2]);
                split_tf(Qs[(r + 8) * 68 + k + 4], ah[mt][3], al[mt][3]);
            }
#pragma unroll
            for (int nt = 0; nt < 4; nt++) {
                int n = wn + nt * 8 + g;
                int k = ks * 8 + q;
                split_tf(KPs[k * 68 + n],       bh_[nt][0], bl[nt][0]);
                split_tf(KPs[(k + 4) * 68 + n], bh_[nt][1], bl[nt][1]);
            }
#pragma unroll
            for (int mt = 0; mt < 2; mt++)
#pragma unroll
                for (int nt = 0; nt < 4; nt++) {
                    mma8(c[mt][nt], ah[mt], bh_[nt]);
                    mma8(c[mt][nt], ah[mt], bl[nt]);
                    mma8(c[mt][nt], al[mt], bh_[nt]);
                }
        }

        // ---- online softmax ----
        float tmax[4] = {-1e30f, -1e30f, -1e30f, -1e30f};
#pragma unroll
        for (int mt = 0; mt < 2; mt++)
#pragma unroll
            for (int nt = 0; nt < 4; nt++)
#pragma unroll
                for (int e = 0; e < 4; e++)
                    tmax[mt * 2 + (e >> 1)] = fmaxf(tmax[mt * 2 + (e >> 1)], c[mt][nt][e]);
#pragma unroll
        for (int s = 1; s < 4; s <<= 1)
#pragma unroll
            for (int i = 0; i < 4; i++)
                tmax[i] = fmaxf(tmax[i], __shfl_xor_sync(0xffffffffu, tmax[i], s));
        if (q == 0) {
#pragma unroll
            for (int i = 0; i < 4; i++)
                red[(warp & 1) * 64 + wm + (i >> 1) * 16 + (i & 1) * 8 + g] = tmax[i];
        }
        __syncthreads();
        float scale[4];
#pragma unroll
        for (int i = 0; i < 4; i++) {
            int rr = wm + (i >> 1) * 16 + (i & 1) * 8 + g;
            float tm = fmaxf(red[rr], red[64 + rr]);
            float mnew = fmaxf(mrun[i], tm);
            scale[i] = expf(mrun[i] - mnew);
            mrun[i] = mnew;
        }
        __syncthreads();   // red reads done before sum-phase writes

        float tsum[4] = {0.f, 0.f, 0.f, 0.f};
#pragma unroll
        for (int mt = 0; mt < 2; mt++)
#pragma unroll
            for (int nt = 0; nt < 4; nt++)
#pragma unroll
                for (int e = 0; e < 4; e++) {
                    int idx = mt * 2 + (e >> 1);
                    float p = expf(c[mt][nt][e] - mrun[idx]);
                    c[mt][nt][e] = p;
                    tsum[idx] += p;
                }
#pragma unroll
        for (int s = 1; s < 4; s <<= 1)
#pragma unroll
            for (int i = 0; i < 4; i++)
                tsum[i] += __shfl_xor_sync(0xffffffffu, tsum[i], s);
        if (q == 0) {
#pragma unroll
            for (int i = 0; i < 4; i++)
                red[(warp & 1) * 64 + wm + (i >> 1) * 16 + (i & 1) * 8 + g] = tsum[i];
        }
        // write P into KPs (K dead after S-MMA; all threads past it)
#pragma unroll
        for (int mt = 0; mt < 2; mt++)
#pragma unroll
            for (int nt = 0; nt < 4; nt++) {
                int row0 = wm + mt * 16 + g;
                int col = wn + nt * 8 + q * 2;
                KPs[row0 * 68 + col] = c[mt][nt][0];
                KPs[row0 * 68 + col + 1] = c[mt][nt][1];
                KPs[(row0 + 8) * 68 + col] = c[mt][nt][2];
                KPs[(row0 + 8) * 68 + col + 1] = c[mt][nt][3];
            }
        __syncthreads();

#pragma unroll
        for (int i = 0; i < 4; i++) {
            int rr = wm + (i >> 1) * 16 + (i & 1) * 8 + g;
            lrun[i] = lrun[i] * scale[i] + red[rr] + red[64 + rr];
        }
        // rescale O, then O += P @ V (single tf32)
#pragma unroll
        for (int mt = 0; mt < 2; mt++)
#pragma unroll
            for (int nt = 0; nt < 4; nt++)
#pragma unroll
                for (int e = 0; e < 4; e++)
                    o[mt][nt][e] *= scale[mt * 2 + (e >> 1)];
#pragma unroll
        for (int ks = 0; ks < 8; ks++) {
            unsigned a[2][4], bb[4][2];
#pragma unroll
            for (int mt = 0; mt < 2; mt++) {
                int r = wm + mt * 16 + g;
                int k = ks * 8 + q;
                a[mt][0] = f2tf(KPs[r * 68 + k]);
                a[mt][1] = f2tf(KPs[(r + 8) * 68 + k]);
                a[mt][2] = f2tf(KPs[r * 68 + k + 4]);
                a[mt][3] = f2tf(KPs[(r + 8) * 68 + k + 4]);
            }
#pragma unroll
            for (int nt = 0; nt < 4; nt++) {
                int n = wn + nt * 8 + g;
                int k = ks * 8 + q;
                bb[nt][0] = f2tf(Vs[k * 68 + n]);
                bb[nt][1] = f2tf(Vs[(k + 4) * 68 + n]);
            }
#pragma unroll
            for (int mt = 0; mt < 2; mt++)
#pragma unroll
                for (int nt = 0; nt < 4; nt++)
                    mma8(o[mt][nt], a[mt], bb[nt]);
        }
    }

    // epilogue: O /= l, write to attn concat [b][i][h*64+d]
    float* Og = O + ((size_t)(b * NN + i0)) * FF + h * DD;
#pragma unroll
    for (int mt = 0; mt < 2; mt++) {
        float il0 = 1.0f / lrun[mt * 2];
        float il1 = 1.0f / lrun[mt * 2 + 1];
#pragma unroll
        for (int nt = 0; nt < 4; nt++) {
            int row0 = wm + mt * 16 + g;
            int col = wn + nt * 8 + q * 2;
            float2 v0 = {o[mt][nt][0] * il0, o[mt][nt][1] * il0};
            *(float2*)(Og + (size_t)row0 * FF + col) = v0;
            float2 v1 = {o[mt][nt][2] * il1, o[mt][nt][3] * il1};
            *(float2*)(Og + (size_t)(row0 + 8) * FF + col) = v1;
        }
    }
}

// ---------------- out = LayerNorm(A + bias + sum_p part[p]) ----------------
template <int P>
__global__ void add_lnp_kernel(const float* __restrict__ A, const float* __restrict__ part,
                               const float* __restrict__ bias,
                               const float* __restrict__ g, const float* __restrict__ be,
                               float* __restrict__ out) {
    int row = blockIdx.x, t = threadIdx.x;
    const float* a = A + (size_t)row * FF;
    __shared__ float red[256];
    float v[4];
    float s = 0.f;
#pragma unroll
    for (int k = 0; k < 4; k++) {
        int c = t + k * 256;
        float acc = a[c] + bias[c];
#pragma unroll
        for (int p = 0; p < P; p++)
            acc += part[(size_t)p * BB * NN * FF + (size_t)row * FF + c];
        v[k] = acc;
        s += acc;
    }
    red[t] = s;
    __syncthreads();
#pragma unroll
    for (int st = 128; st > 0; st >>= 1) {
        if (t < st) red[t] += red[t + st];
        __syncthreads();
    }
    float mean = red[0] * (1.0f / FF);
    __syncthreads();
    float sq = 0.f;
#pragma unroll
    for (int k = 0; k < 4; k++) {
        float d = v[k] - mean;
        sq += d * d;
    }
    red[t] = sq;
    __syncthreads();
#pragma unroll
    for (int st = 128; st > 0; st >>= 1) {
        if (t < st) red[t] += red[t + st];
        __syncthreads();
    }
    float inv = rsqrtf(red[0] * (1.0f / FF) + 1e-5f);
#pragma unroll
    for (int k = 0; k < 4; k++) {
        int c = t + k * 256;
        out[(size_t)row * FF + c] = (v[k] - mean) * inv * g[c] + be[c];
    }
}

// ---------------- launch ----------------
extern "C" void kernel_launch(void* const* d_in, const int* in_sizes, int n_in,
                              void* d_out, int out_size) {
    const float* nfeat      = (const float*)d_in[0];
    const int*   sp_dist    = (const int*)d_in[1];
    const float* rd_dist    = (const float*)d_in[2];
    const float* dist_table = (const float*)d_in[3];
    const float* g_means    = (const float*)d_in[4];
    const float* g_stds     = (const float*)d_in[5];
    const float* g_mul      = (const float*)d_in[6];
    const float* g_biasv    = (const float*)d_in[7];
    const float* mlp_w1     = (const float*)d_in[8];
    const float* mlp_b1     = (const float*)d_in[9];
    const float* mlp_w2     = (const float*)d_in[10];
    const float* mlp_b2     = (const float*)d_in[11];
    const float* wq = (const float*)d_in[12];  const float* bq = (const float*)d_in[13];
    const float* wk = (const float*)d_in[14];  const float* bk = (const float*)d_in[15];
    const float* wv = (const float*)d_in[16];  const float* bv = (const float*)d_in[17];
    const float* wo = (const float*)d_in[18];  const float* bo = (const float*)d_in[19];
    const float* ffn_w1 = (const float*)d_in[20]; const float* ffn_b1 = (const float*)d_in[21];
    const float* ffn_w2 = (const float*)d_in[22]; const float* ffn_b2 = (const float*)d_in[23];
    const float* ln1_g = (const float*)d_in[24]; const float* ln1_b = (const float*)d_in[25];
    const float* ln2_g = (const float*)d_in[26]; const float* ln2_b = (const float*)d_in[27];

    void *pS, *pQ, *pK, *pV, *pAttn, *pX1, *pHid, *pPart;
    cudaGetSymbolAddress(&pS, g_S);
    cudaGetSymbolAddress(&pQ, g_q);
    cudaGetSymbolAddress(&pK, g_k);
    cudaGetSymbolAddress(&pV, g_v);
    cudaGetSymbolAddress(&pAttn, g_attn);
    cudaGetSymbolAddress(&pX1, g_x1);
    cudaGetSymbolAddress(&pHid, g_hid);
    cudaGetSymbolAddress(&pPart, g_part);

    float* S = (float*)pS; float* Q = (float*)pQ; float* Kb = (float*)pK;
    float* V = (float*)pV; float* At = (float*)pAttn;
    float* X1 = (float*)pX1; float* Hd = (float*)pHid;
    float* Pt = (float*)pPart;

    static cudaStream_t s1;
    static cudaEvent_t evFork, evJoin;
    static bool init_done = false;
    if (!init_done) {
        cudaFuncSetAttribute(attn_kernel, cudaFuncAttributeMaxDynamicSharedMemorySize,
                             ATTN_SMEM);
        cudaStreamCreateWithFlags(&s1, cudaStreamNonBlocking);
        cudaEventCreateWithFlags(&evFork, cudaEventDisableTiming);
        cudaEventCreateWithFlags(&evJoin, cudaEventDisableTiming);
        init_done = true;
    }

    // fork: dist-encoder bias on s1, QKV on main stream (independent)
    cudaEventRecord(evFork, 0);
    cudaStreamWaitEvent(s1, evFork, 0);
    bias_kernel<<<BB * NN, 256, 0, s1>>>(sp_dist, rd_dist, g_means, g_stds, g_mul,
                                         g_biasv, dist_table, mlp_w1, mlp_b1,
                                         mlp_w2, mlp_b2, S);
    cudaEventRecord(evJoin, s1);

    // QKV projections on main stream (q scaled by sqrt(D)=8 per reference)
    qkv_gemm<<<dim3(48, 16), 128>>>(nfeat, wq, wk, wv, bq, bk, bv, Q, Kb, V);

    // join: attention needs both bias (s1) and QKV (main)
    cudaStreamWaitEvent(0, evJoin, 0);
    attn_kernel<<<dim3(4, BB * HH), 128, ATTN_SMEM>>>(Q, Kb, V, S, At);

    // output projection (split-K=4 partials) + LN1
    mma_gemm<3><<<dim3(16, 16, 4), 128>>>(At, wo, nullptr, Pt, FF, FF, FF, FF / 4);
    add_lnp_kernel<4><<<BB * NN, 256>>>(nfeat, Pt, bo, ln1_g, ln1_b, X1);

    // FFN: w1+relu direct, w2 split-K=4 partials + LN2
    mma_gemm<1><<<dim3(64, 16, 1), 128>>>(X1, ffn_w1, ffn_b1, Hd, HID, FF, HID, FF);
    mma_gemm<3><<<dim3(16, 16, 4), 128>>>(Hd, ffn_w2, nullptr, Pt, FF, HID, FF, HID / 4);
    add_lnp_kernel<4><<<BB * NN, 256>>>(X1, Pt, ffn_b2, ln2_g, ln2_b, (float*)d_out);
}

// round 11
// speedup vs baseline: 1.0956x; 1.0369x over previous
#include <cuda_runtime.h>
#include <cstdint>
#include <cstddef>
#include <math.h>

// Problem constants
#define BB 4
#define NN 256
#define FF 1024
#define HH 16
#define KK 128
#define DD 64
#define HID 4096
#define TAB 32

// ---------------- scratch (device globals; no allocation) ----------------
__device__ float g_S[(size_t)BB * HH * NN * NN];
__device__ float g_q[(size_t)BB * HH * NN * DD];
__device__ float g_k[(size_t)BB * HH * NN * DD];
__device__ float g_v[(size_t)BB * HH * NN * DD];
__device__ float g_attn[(size_t)BB * NN * FF];
__device__ float g_x1[(size_t)BB * NN * FF];
__device__ float g_hid[(size_t)BB * NN * HID];
__device__ float g_part[(size_t)8 * BB * NN * FF];   // split-K partials (8 planes)
__device__ float g_t1[TAB * HH];

// ---------------- T1 precompute ----------------
__global__ void t1_kernel(const float* __restrict__ dist_table,
                          const float* __restrict__ mlp_w1,
                          const float* __restrict__ mlp_b1,
                          float* __restrict__ t1) {
    int t = threadIdx.x;            // 512 threads
    int sp = t >> 4, h = t & 15;
    float s = mlp_b1[h];
    for (int k = 0; k < KK; k++)
        s += dist_table[sp * KK + k] * mlp_w1[k * HH + h];
    t1[t] = s;
}

// ---------------- bias kernel ----------------
__global__ void bias_kernel(const int* __restrict__ sp_dist,
                            const float* __restrict__ rd_dist,
                            const float* __restrict__ g_means,
                            const float* __restrict__ g_stds,
                            const float* __restrict__ g_mulp,
                            const float* __restrict__ g_biasp,
                            const float* __restrict__ mlp_w1,
                            const float* __restrict__ mlp_w2,
                            const float* __restrict__ mlp_b2,
                            const float* __restrict__ t1,
                            float* __restrict__ S) {
    __shared__ float w1r[KK][HH];
    __shared__ float t1s[TAB][HH];
    __shared__ float w2s[HH][HH];
    __shared__ float mean_s[KK], istd_s[KK], coef_s[KK];
    __shared__ float b2s[HH];

    int t = threadIdx.x;   // 256
    for (int idx = t; idx < KK * HH; idx += 256)
        w1r[idx >> 4][idx & 15] = mlp_w1[(KK + (idx >> 4)) * HH + (idx & 15)];
    for (int idx = t; idx < TAB * HH; idx += 256)
        t1s[idx >> 4][idx & 15] = t1[idx];
    if (t < HH * HH) w2s[t >> 4][t & 15] = mlp_w2[t];
    if (t < KK) {
        float s = fabsf(g_stds[t]) + 0.01f;
        istd_s[t] = 1.0f / s;
        coef_s[t] = 1.0f / (sqrtf(2.0f * 3.14159f) * s);
        mean_s[t] = g_means[t];
    }
    if (t < HH) b2s[t] = mlp_b2[t];
    __syncthreads();

    int bi = blockIdx.x;                    // b*N + i
    int j = t;
    size_t idx = (size_t)bi * NN + j;
    int sp = sp_dist[idx];
    float rd = rd_dist[idx];
    float x = g_mulp[0] * rd + g_biasp[0];

    float acc[HH];
#pragma unroll
    for (int h = 0; h < HH; h++) acc[h] = t1s[sp][h];

    for (int k = 0; k < KK; k++) {
        float dd = (x - mean_s[k]) * istd_s[k];
        float g = expf(-0.5f * dd * dd) * coef_s[k];
#pragma unroll
        for (int h = 0; h < HH; h++) acc[h] += g * w1r[k][h];
    }
#pragma unroll
    for (int h = 0; h < HH; h++) {
        float a = acc[h];
        acc[h] = 0.5f * a * (1.0f + erff(a * 0.70710678118654752f));
    }

    int b = bi >> 8, i = bi & 255;
#pragma unroll
    for (int h2 = 0; h2 < HH; h2++) {
        float o = b2s[h2];
#pragma unroll
        for (int h = 0; h < HH; h++) o += acc[h] * w2s[h][h2];
        S[(((size_t)(b * HH + h2) * NN + i) * NN) + j] = o;
    }
}

// ---------------- TF32 helpers ----------------
__device__ __forceinline__ unsigned f2tf(float f) {
    unsigned u;
    asm("cvt.rna.tf32.f32 %0, %1;" : "=r"(u) : "f"(f));
    return u;
}
__device__ __forceinline__ void split_tf(float f, unsigned& hi, unsigned& lo) {
    hi = f2tf(f);
    lo = f2tf(f - __uint_as_float(hi));
}
__device__ __forceinline__ void mma8(float (&c)[4], const unsigned* a, const unsigned* b) {
    asm volatile(
        "mma.sync.aligned.m16n8k8.row.col.f32.tf32.tf32.f32 "
        "{%0,%1,%2,%3},{%4,%5,%6,%7},{%8,%9},{%0,%1,%2,%3};"
        : "+f"(c[0]), "+f"(c[1]), "+f"(c[2]), "+f"(c[3])
        : "r"(a[0]), "r"(a[1]), "r"(a[2]), "r"(a[3]), "r"(b[0]), "r"(b[1]));
}

// ---------------- TF32 MMA core: 64x64 tile, BK=32, 128 threads ----------------
__device__ __forceinline__ void mma_core(
    const float* __restrict__ Ag, int lda,
    const float* __restrict__ Bg, int ldb, int kLen,
    float (*As)[64][36], float (*Bs)[32][68], float (&c)[2][4][4]) {
    int t = threadIdx.x;
    int warp = t >> 5, lane = t & 31;
    int g = lane >> 2, q = lane & 3;
    int wm = (warp >> 1) * 32, wn = (warp & 1) * 32;

#pragma unroll
    for (int i = 0; i < 2; i++)
#pragma unroll
        for (int j = 0; j < 4; j++)
#pragma unroll
            for (int e = 0; e < 4; e++) c[i][j][e] = 0.f;

    const int KT = kLen / 32;

    auto load_tile = [&](int bufi, int k0) {
#pragma unroll
        for (int i_ = 0; i_ < 4; i_++) {
            int id = t + i_ * 128;
            int row = id >> 3, c4 = id & 7;
            const float* src = Ag + (size_t)row * lda + k0 + c4 * 4;
            unsigned dst = (unsigned)__cvta_generic_to_shared(&As[bufi][row][c4 * 4]);
            asm volatile("cp.async.ca.shared.global [%0], [%1], 16;\n" ::"r"(dst), "l"(src));
        }
#pragma unroll
        for (int i_ = 0; i_ < 4; i_++) {
            int id = t + i_ * 128;
            int row = id >> 4, c4 = id & 15;
            const float* src = Bg + (size_t)(k0 + row) * ldb + c4 * 4;
            unsigned dst = (unsigned)__cvta_generic_to_shared(&Bs[bufi][row][c4 * 4]);
            asm volatile("cp.async.ca.shared.global [%0], [%1], 16;\n" ::"r"(dst), "l"(src));
        }
        asm volatile("cp.async.commit_group;\n" ::);
    };

    load_tile(0, 0);

    for (int kt = 0; kt < KT; kt++) {
        int buf = kt & 1;
        if (kt + 1 < KT) {
            load_tile(buf ^ 1, (kt + 1) * 32);
            asm volatile("cp.async.wait_group 1;\n" ::);
        } else {
            asm volatile("cp.async.wait_group 0;\n" ::);
        }
        __syncthreads();

#pragma unroll
        for (int ks = 0; ks < 4; ks++) {
            unsigned a[2][4], b[4][2];
#pragma unroll
            for (int mt = 0; mt < 2; mt++) {
                int r = wm + mt * 16 + g;
                int k = ks * 8 + q;
                a[mt][0] = f2tf(As[buf][r][k]);
                a[mt][1] = f2tf(As[buf][r + 8][k]);
                a[mt][2] = f2tf(As[buf][r][k + 4]);
                a[mt][3] = f2tf(As[buf][r + 8][k + 4]);
            }
#pragma unroll
            for (int nt = 0; nt < 4; nt++) {
                int n = wn + nt * 8 + g;
                int k = ks * 8 + q;
                b[nt][0] = f2tf(Bs[buf][k][n]);
                b[nt][1] = f2tf(Bs[buf][k + 4][n]);
            }
#pragma unroll
            for (int mt = 0; mt < 2; mt++)
#pragma unroll
                for (int nt = 0; nt < 4; nt++)
                    mma8(c[mt][nt], a[mt], b[nt]);
        }
        __syncthreads();
    }
}

// ---------------- generic GEMM: MODE 0 plain+bias, 1 relu+bias, 3 raw partial ----
template <int MODE>
__global__ void __launch_bounds__(128) mma_gemm(
    const float* __restrict__ A, const float* __restrict__ B,
    const float* __restrict__ bias, float* __restrict__ C,
    int N, int lda, int ldb, int kLen) {
    __shared__ float As[2][64][36];
    __shared__ float Bs[2][32][68];
    int m0 = blockIdx.y * 64, n0 = blockIdx.x * 64;

    int z = blockIdx.z;
    const float* Ag = A + (size_t)m0 * lda + (size_t)z * kLen;
    const float* Bg = B + (size_t)z * kLen * ldb + n0;
    float* Cg = (MODE == 3) ? C + (size_t)z * gridDim.y * 64 * N : C;

    float c[2][4][4];
    mma_core(Ag, lda, Bg, ldb, kLen, As, Bs, c);

    int t = threadIdx.x;
    int warp = t >> 5, lane = t & 31;
    int g = lane >> 2, q = lane & 3;
    int wm = (warp >> 1) * 32, wn = (warp & 1) * 32;

#pragma unroll
    for (int mt = 0; mt < 2; mt++)
#pragma unroll
        for (int nt = 0; nt < 4; nt++)
#pragma unroll
            for (int e = 0; e < 4; e++) {
                int row = m0 + wm + mt * 16 + g + ((e >= 2) ? 8 : 0);
                int col = n0 + wn + nt * 8 + q * 2 + (e & 1);
                float v = c[mt][nt][e];
                if (MODE != 3) v += bias[col];
                if (MODE == 1) v = fmaxf(v, 0.f);
                Cg[(size_t)row * N + col] = v;
            }
}

// ---------------- fused QKV GEMM: grid (48, 16) ----------------
__global__ void __launch_bounds__(128) qkv_gemm(
    const float* __restrict__ A,
    const float* __restrict__ wq, const float* __restrict__ wk, const float* __restrict__ wv,
    const float* __restrict__ bq, const float* __restrict__ bk, const float* __restrict__ bv,
    float* __restrict__ Qo, float* __restrict__ Ko, float* __restrict__ Vo) {
    __shared__ float As[2][64][36];
    __shared__ float Bs[2][32][68];
    int mat = blockIdx.x >> 4;
    int n0 = (blockIdx.x & 15) * 64, m0 = blockIdx.y * 64;
    const float* B = (mat == 0) ? wq : (mat == 1) ? wk : wv;
    const float* bias = (mat == 0) ? bq : (mat == 1) ? bk : bv;
    float* C = (mat == 0) ? Qo : (mat == 1) ? Ko : Vo;
    float scale = (mat == 0) ? 8.0f : 1.0f;

    const float* Ag = A + (size_t)m0 * FF;
    const float* Bg = B + n0;

    float c[2][4][4];
    mma_core(Ag, FF, Bg, FF, FF, As, Bs, c);

    int t = threadIdx.x;
    int warp = t >> 5, lane = t & 31;
    int g = lane >> 2, q = lane & 3;
    int wm = (warp >> 1) * 32, wn = (warp & 1) * 32;

#pragma unroll
    for (int mt = 0; mt < 2; mt++)
#pragma unroll
        for (int nt = 0; nt < 4; nt++)
#pragma unroll
            for (int e = 0; e < 4; e++) {
                int row = m0 + wm + mt * 16 + g + ((e >= 2) ? 8 : 0);
                int col = n0 + wn + nt * 8 + q * 2 + (e & 1);
                float v = (c[mt][nt][e] + bias[col]) * scale;
                int b_ = row >> 8, ii = row & 255, h = col >> 6, d = col & 63;
                C[(((size_t)(b_ * HH + h) * NN + ii) * DD) + d] = v;
            }
}

// ---------------- fused flash attention, 32-row i-tiles ----------------
// grid (8, 64): blockIdx.x = i-tile (32 rows), blockIdx.y = b*H+h. 128 threads.
// Warps 2x2 over the 32x64 S tile: warp tile 16x32.
#define ATTN_SMEM ((32 * 68 + 2 * 64 * 68 + 64) * 4)
__global__ void __launch_bounds__(128) attn_kernel(
    const float* __restrict__ Q, const float* __restrict__ K,
    const float* __restrict__ V, const float* __restrict__ Sb,
    float* __restrict__ O) {
    extern __shared__ float sm[];
    float* Qs  = sm;                        // [32][68]  Q tile  [i][d]
    float* KPs = sm + 32 * 68;              // [64][68]  K^T [d][j], then P [i][j]
    float* Vs  = sm + 32 * 68 + 64 * 68;    // [64][68]  V tile [j][d]
    float* red = sm + 32 * 68 + 2 * 64 * 68; // [2][32]  cross-warp row reduction

    int bh = blockIdx.y;
    int b = bh >> 4, h = bh & 15;
    int i0 = blockIdx.x * 32;
    const float* Qg = Q + (size_t)bh * NN * DD + (size_t)i0 * DD;
    const float* Kg = K + (size_t)bh * NN * DD;
    const float* Vg = V + (size_t)bh * NN * DD;
    const float* Bg = Sb + (size_t)bh * NN * NN + (size_t)i0 * NN;

    int t = threadIdx.x;
    int warp = t >> 5, lane = t & 31;
    int g = lane >> 2, q = lane & 3;
    int wm = (warp >> 1) * 16, wn = (warp & 1) * 32;
    int r0 = wm + g, r1 = wm + g + 8;

    // load Q tile [32][64]
#pragma unroll
    for (int r = 0; r < 4; r++) {
        int id = t + r * 128;
        int row = id >> 4, c4 = (id & 15) * 4;
        *(float4*)&Qs[row * 68 + c4] = *(const float4*)(Qg + (size_t)row * DD + c4);
    }

    float o[4][4];
#pragma unroll
    for (int nt = 0; nt < 4; nt++)
#pragma unroll
        for (int e = 0; e < 4; e++) o[nt][e] = 0.f;
    float mrun[2] = {-1e30f, -1e30f};
    float lrun[2] = {0.f, 0.f};

    for (int jt = 0; jt < 4; jt++) {
        int j0 = jt * 64;
        __syncthreads();    // prior PV reads of KPs/Vs done; Qs ready
        // K^T tile: KPs[d][j] = K[j0+j][d]
#pragma unroll
        for (int r = 0; r < 8; r++) {
            int id = t + r * 128;
            int row = id >> 4, c4 = (id & 15) * 4;
            float4 kv = *(const float4*)(Kg + (size_t)(j0 + row) * DD + c4);
            KPs[(c4 + 0) * 68 + row] = kv.x;
            KPs[(c4 + 1) * 68 + row] = kv.y;
            KPs[(c4 + 2) * 68 + row] = kv.z;
            KPs[(c4 + 3) * 68 + row] = kv.w;
        }
        // V tile: Vs[j][d]
#pragma unroll
        for (int r = 0; r < 8; r++) {
            int id = t + r * 128;
            int row = id >> 4, c4 = (id & 15) * 4;
            *(float4*)&Vs[row * 68 + c4] = *(const float4*)(Vg + (size_t)(j0 + row) * DD + c4);
        }
        __syncthreads();

        // init c with bias fragment
        float c[4][4];
#pragma unroll
        for (int nt = 0; nt < 4; nt++) {
            int col = j0 + wn + nt * 8 + q * 2;
            float2 b0 = *(const float2*)(Bg + (size_t)r0 * NN + col);
            float2 b1 = *(const float2*)(Bg + (size_t)r1 * NN + col);
            c[nt][0] = b0.x; c[nt][1] = b0.y;
            c[nt][2] = b1.x; c[nt][3] = b1.y;
        }

        // S += Q @ K^T via 3xTF32 (hi*hi + hi*lo + lo*hi)
#pragma unroll
        for (int ks = 0; ks < 8; ks++) {
            int k = ks * 8 + q;
            unsigned ah[4], al[4], bh_[4][2], bl[4][2];
            split_tf(Qs[r0 * 68 + k],     ah[0], al[0]);
            split_tf(Qs[r1 * 68 + k],     ah[1], al[1]);
            split_tf(Qs[r0 * 68 + k + 4], ah[2], al[2]);
            split_tf(Qs[r1 * 68 + k + 4], ah[3], al[3]);
#pragma unroll
            for (int nt = 0; nt < 4; nt++) {
                int n = wn + nt * 8 + g;
                split_tf(KPs[k * 68 + n],       bh_[nt][0], bl[nt][0]);
                split_tf(KPs[(k + 4) * 68 + n], bh_[nt][1], bl[nt][1]);
            }
#pragma unroll
            for (int nt = 0; nt < 4; nt++) {
                mma8(c[nt], ah, bh_[nt]);
                mma8(c[nt], ah, bl[nt]);
                mma8(c[nt], al, bh_[nt]);
            }
        }

        // ---- online softmax ----
        float tmax[2] = {-1e30f, -1e30f};
#pragma unroll
        for (int nt = 0; nt < 4; nt++)
#pragma unroll
            for (int e = 0; e < 4; e++)
                tmax[e >> 1] = fmaxf(tmax[e >> 1], c[nt][e]);
#pragma unroll
        for (int s = 1; s < 4; s <<= 1)
#pragma unroll
            for (int i = 0; i < 2; i++)
                tmax[i] = fmaxf(tmax[i], __shfl_xor_sync(0xffffffffu, tmax[i], s));
        if (q == 0) {
            red[(warp & 1) * 32 + r0] = tmax[0];
            red[(warp & 1) * 32 + r1] = tmax[1];
        }
        __syncthreads();
        float scale[2];
#pragma unroll
        for (int i = 0; i < 2; i++) {
            int rr = wm + i * 8 + g;
            float tm = fmaxf(red[rr], red[32 + rr]);
            float mnew = fmaxf(mrun[i], tm);
            scale[i] = expf(mrun[i] - mnew);
            mrun[i] = mnew;
        }
        __syncthreads();   // red reads done before sum-phase writes

        float tsum[2] = {0.f, 0.f};
#pragma unroll
        for (int nt = 0; nt < 4; nt++)
#pragma unroll
            for (int e = 0; e < 4; e++) {
                float p = expf(c[nt][e] - mrun[e >> 1]);
                c[nt][e] = p;
                tsum[e >> 1] += p;
            }
#pragma unroll
        for (int s = 1; s < 4; s <<= 1)
#pragma unroll
            for (int i = 0; i < 2; i++)
                tsum[i] += __shfl_xor_sync(0xffffffffu, tsum[i], s);
        if (q == 0) {
            red[(warp & 1) * 32 + r0] = tsum[0];
            red[(warp & 1) * 32 + r1] = tsum[1];
        }
        // write P into KPs (K dead after S-MMA; all threads past it)
#pragma unroll
        for (int nt = 0; nt < 4; nt++) {
            int col = wn + nt * 8 + q * 2;
            KPs[r0 * 68 + col]     = c[nt][0];
            KPs[r0 * 68 + col + 1] = c[nt][1];
            KPs[r1 * 68 + col]     = c[nt][2];
            KPs[r1 * 68 + col + 1] = c[nt][3];
        }
        __syncthreads();

#pragma unroll
        for (int i = 0; i < 2; i++) {
            int rr = wm + i * 8 + g;
            lrun[i] = lrun[i] * scale[i] + red[rr] + red[32 + rr];
        }
        // rescale O, then O += P @ V (single tf32)
#pragma unroll
        for (int nt = 0; nt < 4; nt++)
#pragma unroll
            for (int e = 0; e < 4; e++)
                o[nt][e] *= scale[e >> 1];
#pragma unroll
        for (int ks = 0; ks < 8; ks++) {
            int k = ks * 8 + q;
            unsigned a[4], bb[4][2];
            a[0] = f2tf(KPs[r0 * 68 + k]);
            a[1] = f2tf(KPs[r1 * 68 + k]);
            a[2] = f2tf(KPs[r0 * 68 + k + 4]);
            a[3] = f2tf(KPs[r1 * 68 + k + 4]);
#pragma unroll
            for (int nt = 0; nt < 4; nt++) {
                int n = wn + nt * 8 + g;
                bb[nt][0] = f2tf(Vs[k * 68 + n]);
                bb[nt][1] = f2tf(Vs[(k + 4) * 68 + n]);
            }
#pragma unroll
            for (int nt = 0; nt < 4; nt++)
                mma8(o[nt], a, bb[nt]);
        }
    }

    // epilogue: O /= l, write to attn concat [b][i][h*64+d]
    float* Og = O + ((size_t)(b * NN + i0)) * FF + h * DD;
    float il0 = 1.0f / lrun[0];
    float il1 = 1.0f / lrun[1];
#pragma unroll
    for (int nt = 0; nt < 4; nt++) {
        int col = wn + nt * 8 + q * 2;
        float2 v0 = {o[nt][0] * il0, o[nt][1] * il0};
        *(float2*)(Og + (size_t)r0 * FF + col) = v0;
        float2 v1 = {o[nt][2] * il1, o[nt][3] * il1};
        *(float2*)(Og + (size_t)r1 * FF + col) = v1;
    }
}

// ---------------- out = LayerNorm(A + bias + sum_p part[p]) ----------------
template <int P>
__global__ void add_lnp_kernel(const float* __restrict__ A, const float* __restrict__ part,
                               const float* __restrict__ bias,
                               const float* __restrict__ g, const float* __restrict__ be,
                               float* __restrict__ out) {
    int row = blockIdx.x, t = threadIdx.x;
    const float* a = A + (size_t)row * FF;
    __shared__ float red[256];
    float v[4];
    float s = 0.f;
#pragma unroll
    for (int k = 0; k < 4; k++) {
        int c = t + k * 256;
        float acc = a[c] + bias[c];
#pragma unroll
        for (int p = 0; p < P; p++)
            acc += part[(size_t)p * BB * NN * FF + (size_t)row * FF + c];
        v[k] = acc;
        s += acc;
    }
    red[t] = s;
    __syncthreads();
#pragma unroll
    for (int st = 128; st > 0; st >>= 1) {
        if (t < st) red[t] += red[t + st];
        __syncthreads();
    }
    float mean = red[0] * (1.0f / FF);
    __syncthreads();
    float sq = 0.f;
#pragma unroll
    for (int k = 0; k < 4; k++) {
        float d = v[k] - mean;
        sq += d * d;
    }
    red[t] = sq;
    __syncthreads();
#pragma unroll
    for (int st = 128; st > 0; st >>= 1) {
        if (t < st) red[t] += red[t + st];
        __syncthreads();
    }
    float inv = rsqrtf(red[0] * (1.0f / FF) + 1e-5f);
#pragma unroll
    for (int k = 0; k < 4; k++) {
        int c = t + k * 256;
        out[(size_t)row * FF + c] = (v[k] - mean) * inv * g[c] + be[c];
    }
}

// ---------------- launch ----------------
extern "C" void kernel_launch(void* const* d_in, const int* in_sizes, int n_in,
                              void* d_out, int out_size) {
    const float* nfeat      = (const float*)d_in[0];
    const int*   sp_dist    = (const int*)d_in[1];
    const float* rd_dist    = (const float*)d_in[2];
    const float* dist_table = (const float*)d_in[3];
    const float* g_means    = (const float*)d_in[4];
    const float* g_stds     = (const float*)d_in[5];
    const float* g_mul      = (const float*)d_in[6];
    const float* g_biasv    = (const float*)d_in[7];
    const float* mlp_w1     = (const float*)d_in[8];
    const float* mlp_b1     = (const float*)d_in[9];
    const float* mlp_w2     = (const float*)d_in[10];
    const float* mlp_b2     = (const float*)d_in[11];
    const float* wq = (const float*)d_in[12];  const float* bq = (const float*)d_in[13];
    const float* wk = (const float*)d_in[14];  const float* bk = (const float*)d_in[15];
    const float* wv = (const float*)d_in[16];  const float* bv = (const float*)d_in[17];
    const float* wo = (const float*)d_in[18];  const float* bo = (const float*)d_in[19];
    const float* ffn_w1 = (const float*)d_in[20]; const float* ffn_b1 = (const float*)d_in[21];
    const float* ffn_w2 = (const float*)d_in[22]; const float* ffn_b2 = (const float*)d_in[23];
    const float* ln1_g = (const float*)d_in[24]; const float* ln1_b = (const float*)d_in[25];
    const float* ln2_g = (const float*)d_in[26]; const float* ln2_b = (const float*)d_in[27];

    void *pS, *pQ, *pK, *pV, *pAttn, *pX1, *pHid, *pPart, *pT1;
    cudaGetSymbolAddress(&pS, g_S);
    cudaGetSymbolAddress(&pQ, g_q);
    cudaGetSymbolAddress(&pK, g_k);
    cudaGetSymbolAddress(&pV, g_v);
    cudaGetSymbolAddress(&pAttn, g_attn);
    cudaGetSymbolAddress(&pX1, g_x1);
    cudaGetSymbolAddress(&pHid, g_hid);
    cudaGetSymbolAddress(&pPart, g_part);
    cudaGetSymbolAddress(&pT1, g_t1);

    float* S = (float*)pS; float* Q = (float*)pQ; float* Kb = (float*)pK;
    float* V = (float*)pV; float* At = (float*)pAttn;
    float* X1 = (float*)pX1; float* Hd = (float*)pHid;
    float* Pt = (float*)pPart; float* T1 = (float*)pT1;

    static cudaStream_t s1;
    static cudaEvent_t evFork, evJoin;
    static bool init_done = false;
    if (!init_done) {
        cudaFuncSetAttribute(attn_kernel, cudaFuncAttributeMaxDynamicSharedMemorySize,
                             ATTN_SMEM);
        cudaStreamCreateWithFlags(&s1, cudaStreamNonBlocking);
        cudaEventCreateWithFlags(&evFork, cudaEventDisableTiming);
        cudaEventCreateWithFlags(&evJoin, cudaEventDisableTiming);
        init_done = true;
    }

    // fork: dist-encoder chain on s1, QKV on main stream (independent)
    cudaEventRecord(evFork, 0);
    cudaStreamWaitEvent(s1, evFork, 0);
    t1_kernel<<<1, 512, 0, s1>>>(dist_table, mlp_w1, mlp_b1, T1);
    bias_kernel<<<BB * NN, 256, 0, s1>>>(sp_dist, rd_dist, g_means, g_stds, g_mul,
                                         g_biasv, mlp_w1, mlp_w2, mlp_b2, T1, S);
    cudaEventRecord(evJoin, s1);

    // QKV projections on main stream (q scaled by sqrt(D)=8 per reference)
    qkv_gemm<<<dim3(48, 16), 128>>>(nfeat, wq, wk, wv, bq, bk, bv, Q, Kb, V);

    // join: attention needs both bias (s1) and QKV (main)
    cudaStreamWaitEvent(0, evJoin, 0);
    attn_kernel<<<dim3(8, BB * HH), 128, ATTN_SMEM>>>(Q, Kb, V, S, At);

    // output projection (split-K=8 partials) + LN1
    mma_gemm<3><<<dim3(16, 16, 8), 128>>>(At, wo, nullptr, Pt, FF, FF, FF, FF / 8);
    add_lnp_kernel<8><<<BB * NN, 256>>>(nfeat, Pt, bo, ln1_g, ln1_b, X1);

    // FFN: w1+relu direct, w2 split-K=8 partials + LN2
    mma_gemm<1><<<dim3(64, 16, 1), 128>>>(X1, ffn_w1, ffn_b1, Hd, HID, FF, HID, FF);
    mma_gemm<3><<<dim3(16, 16, 8), 128>>>(Hd, ffn_w2, nullptr, Pt, FF, HID, FF, HID / 8);
    add_lnp_kernel<8><<<BB * NN, 256>>>(X1, Pt, ffn_b2, ln2_g, ln2_b, (float*)d_out);
}